// round 15
// baseline (speedup 1.0000x reference)
#include <cuda_runtime.h>
#include <cuda_fp16.h>
#include <math.h>
#include <stdint.h>

#define T_TOKENS 4096
#define DIMD     1024
#define INTER    1408
#define SINTER   2816
#define NEXP     16

__device__ int   g_cnt[NEXP];
__device__ int   g_tok[NEXP * T_TOKENS];
__device__ float g_wt [NEXP * T_TOKENS];
__device__ int   g_se [T_TOKENS * 2];
__device__ int   g_sp [T_TOKENS * 2];
__device__ float g_sw [T_TOKENS * 2];
__device__ float g_y  [T_TOKENS * 2 * DIMD];

// pure fp16 storage
__device__ __half s_x [T_TOKENS * DIMD];
__device__ __half s_w1[NEXP * DIMD * INTER];
__device__ __half s_w3[NEXP * DIMD * INTER];
__device__ __half s_w2[NEXP * INTER * DIMD];
__device__ __half s_u1[DIMD * SINTER];
__device__ __half s_u3[DIMD * SINTER];
__device__ __half s_u2[SINTER * DIMD];
__device__ __half s_a [T_TOKENS * 2 * INTER];
__device__ __half s_z [T_TOKENS * SINTER];

__device__ __forceinline__ uint32_t smem_u32(const void* p) {
    uint32_t a;
    asm("{ .reg .u64 t; cvta.to.shared.u64 t, %1; cvt.u32.u64 %0, t; }" : "=r"(a) : "l"(p));
    return a;
}
#define LDSM_X4(R, a) \
    asm volatile("ldmatrix.sync.aligned.m8n8.x4.shared.b16 {%0,%1,%2,%3}, [%4];" \
        : "=r"((R)[0]), "=r"((R)[1]), "=r"((R)[2]), "=r"((R)[3]) : "r"(a))
#define LDSM_X4T(R, a) \
    asm volatile("ldmatrix.sync.aligned.m8n8.x4.trans.shared.b16 {%0,%1,%2,%3}, [%4];" \
        : "=r"((R)[0]), "=r"((R)[1]), "=r"((R)[2]), "=r"((R)[3]) : "r"(a))
#define MMA_F16(C, A, b0, b1) \
    asm volatile("mma.sync.aligned.m16n8k16.row.col.f32.f16.f16.f32 " \
        "{%0,%1,%2,%3},{%4,%5,%6,%7},{%8,%9},{%0,%1,%2,%3};" \
        : "+f"((C)[0]), "+f"((C)[1]), "+f"((C)[2]), "+f"((C)[3]) \
        : "r"((A)[0]), "r"((A)[1]), "r"((A)[2]), "r"((A)[3]), "r"(b0), "r"(b1))
#define CP16(dst, src) \
    asm volatile("cp.async.cg.shared.global [%0], [%1], 16;" :: "r"(dst), "l"(src))
#define CPC()  asm volatile("cp.async.commit_group;")
#define CPW0() asm volatile("cp.async.wait_group 0;")
#define CPW1() asm volatile("cp.async.wait_group 1;")

__device__ __forceinline__ uint32_t pack_h2(float a, float b) {
    __half2 t = __halves2half2(__float2half(a), __float2half(b));
    return *(uint32_t*)&t;
}

#define N1 ((size_t)NEXP * DIMD * INTER / 4)
#define N2 ((size_t)DIMD * SINTER / 4)

// ---------- pre: split w1,w3,u1,u3 + split x + reset g_cnt (all independent) ----------
__global__ void pre_kernel(const float* __restrict__ w1, const float* __restrict__ w3,
                           const float* __restrict__ u1, const float* __restrict__ u3,
                           const float* __restrict__ x)
{
    const size_t BS = (2 * N1 + 2 * N2) / 256;   // split blocks
    size_t b = blockIdx.x;
    if (b < BS) {
        size_t i = b * 256 + threadIdx.x;
        const float* src; __half* h; size_t o;
        if      (i < N1)          { src = w1; h = s_w1; o = i; }
        else if (i < 2*N1)        { src = w3; h = s_w3; o = i - N1; }
        else if (i < 2*N1 + N2)   { src = u1; h = s_u1; o = i - 2*N1; }
        else                      { src = u3; h = s_u3; o = i - 2*N1 - N2; }
        float4 v = *(const float4*)(src + o * 4);
        uint2 H; H.x = pack_h2(v.x, v.y); H.y = pack_h2(v.z, v.w);
        *(uint2*)(h + o * 4) = H;
    } else {
        if (b == BS && threadIdx.x < NEXP) g_cnt[threadIdx.x] = 0;
        size_t i = (b - BS) * 256 + threadIdx.x;
        float4 v = *(const float4*)(x + i * 4);
        uint2 H; H.x = pack_h2(v.x, v.y); H.y = pack_h2(v.z, v.w);
        *(uint2*)(s_x + i * 4) = H;
    }
}

// ---------- gate ----------
__global__ void gate_kernel(const float* __restrict__ x, const float* __restrict__ gw,
                            const float* __restrict__ gb)
{
    int t = blockIdx.x * blockDim.y + threadIdx.y;
    if (t >= T_TOKENS) return;
    int lane = threadIdx.x;
    float acc[NEXP];
#pragma unroll
    for (int e = 0; e < NEXP; e++) acc[e] = 0.f;
    const float* xr = x + (size_t)t * DIMD;
    for (int d = lane; d < DIMD; d += 32) {
        float xv = xr[d];
        const float* g = gw + (size_t)d * NEXP;
#pragma unroll
        for (int e = 0; e < NEXP; e++) acc[e] += xv * g[e];
    }
#pragma unroll
    for (int e = 0; e < NEXP; e++)
#pragma unroll
        for (int o = 16; o > 0; o >>= 1) acc[e] += __shfl_xor_sync(0xffffffffu, acc[e], o);
    if (lane == 0) {
        float mx = -1e30f;
#pragma unroll
        for (int e = 0; e < NEXP; e++) { acc[e] += gb[e]; mx = fmaxf(mx, acc[e]); }
        float s = 0.f;
#pragma unroll
        for (int e = 0; e < NEXP; e++) { acc[e] = expf(acc[e] - mx); s += acc[e]; }
        int b0 = 0; float v0 = -1.f;
#pragma unroll
        for (int e = 0; e < NEXP; e++) if (acc[e] > v0) { v0 = acc[e]; b0 = e; }
        int b1i = -1; float v1 = -1.f;
#pragma unroll
        for (int e = 0; e < NEXP; e++) if (e != b0 && acc[e] > v1) { v1 = acc[e]; b1i = e; }
        float w0 = v0 / s, w1 = v1 / s;
        int p0 = atomicAdd(&g_cnt[b0], 1);
        g_tok[b0 * T_TOKENS + p0] = t;  g_wt[b0 * T_TOKENS + p0] = w0;
        int p1 = atomicAdd(&g_cnt[b1i], 1);
        g_tok[b1i * T_TOKENS + p1] = t; g_wt[b1i * T_TOKENS + p1] = w1;
        g_se[t*2+0] = b0;  g_sp[t*2+0] = p0;  g_sw[t*2+0] = w0;
        g_se[t*2+1] = b1i; g_sp[t*2+1] = p1;  g_sw[t*2+1] = w1;
    }
}

// inline 16-wide prefix: offset of expert e in compact layout
__device__ __forceinline__ int expert_off(int e) {
    int s = 0;
    for (int j = 0; j < e; j++) s += g_cnt[j];
    return s;
}

// ---------- UP: dual-B SwiGLU GEMM, fp16, BK=64, 3-stage, 2 CTAs/SM ----------
// z==NEXP: shared slice. z==NEXP+1: embedded w2/u2 split.
// Inner s-loop phase-rotated by warp id to break the LDSM/MMA convoy.
// Stage (36864 B): A 0 (128 x 144B, 64 k) | B1 18432 (64 x 144B) | B2 27648
__global__ void __launch_bounds__(256, 2)
up_gemm(const float* __restrict__ b1, const float* __restrict__ b3,
        const float* __restrict__ sb1, const float* __restrict__ sb3,
        const float* __restrict__ w2, const float* __restrict__ u2)
{
    extern __shared__ char smem[];
    const int z = blockIdx.z;
    const int tid = threadIdx.x;
    if (z == NEXP + 1) {                        // embedded split of w2 / u2
        const size_t total = N1 + N2;
        size_t base = ((size_t)blockIdx.y * gridDim.x + blockIdx.x) * 256 + tid;
        size_t stride = (size_t)gridDim.x * gridDim.y * 256;
        for (size_t i = base; i < total; i += stride) {
            const float* src; __half* h; size_t o;
            if (i < N1) { src = w2; h = s_w2; o = i; }
            else        { src = u2; h = s_u2; o = i - N1; }
            float4 v = *(const float4*)(src + o * 4);
            uint2 H; H.x = pack_h2(v.x, v.y); H.y = pack_h2(v.z, v.w);
            *(uint2*)(h + o * 4) = H;
        }
        return;
    }
    const bool sh = (z == NEXP);
    if (!sh && blockIdx.x >= INTER / 64) return;
    const int NN = sh ? SINTER : INTER;
    const int n0 = blockIdx.x * 64, m0 = blockIdx.y * 128;
    int M = T_TOKENS, rowbase = 0;
    const int* rowidx = nullptr; const float* wv = nullptr;
    const __half *B1, *B2;
    const float *bias1, *bias2;
    __half* oa;
    if (sh) {
        B1 = s_u1; B2 = s_u3; bias1 = sb1; bias2 = sb3; oa = s_z;
    } else {
        M = g_cnt[z];
        if (m0 >= M) return;
        rowbase = expert_off(z);
        size_t wo = (size_t)z * DIMD * INTER;
        B1 = s_w1 + wo; B2 = s_w3 + wo;
        bias1 = b1 + (size_t)z * INTER; bias2 = b3 + (size_t)z * INTER;
        rowidx = g_tok + z * T_TOKENS; wv = g_wt + z * T_TOKENS;
        oa = s_a;
    }

    const int lane = tid & 31, wid = tid >> 5;
    const int wm = wid >> 2, wn = wid & 3;
    const uint32_t sbase = smem_u32(smem);
    const int SSZ = 36864;
    const int KK = DIMD;

    const __half* ap[4];
    uint32_t adst[4];
#pragma unroll
    for (int it = 0; it < 4; it++) {
        int task = tid + it * 256, row = task >> 3, c = task & 7;
        int r = m0 + row; if (r >= M) r = M - 1;
        size_t ro = rowidx ? (size_t)rowidx[r] * KK : (size_t)r * KK;
        ap[it] = s_x + ro + c * 8;
        adst[it] = row * 144 + c * 16;
    }
    const int bkl0 = tid >> 3, bc = tid & 7;
    const size_t bb0 = (size_t)bkl0 * NN + n0 + bc * 8;
    const size_t bb1 = (size_t)(bkl0 + 32) * NN + n0 + bc * 8;
    const uint32_t bd0 = bkl0 * 144 + bc * 16;
    const uint32_t bd1 = (bkl0 + 32) * 144 + bc * 16;

    auto stage = [&](int k0, int st) {
        uint32_t sp = sbase + st * SSZ;
#pragma unroll
        for (int it = 0; it < 4; it++)
            CP16(sp + adst[it], ap[it] + k0);
        size_t g0 = bb0 + (size_t)k0 * NN, g1 = bb1 + (size_t)k0 * NN;
        CP16(sp + 18432 + bd0, B1 + g0);
        CP16(sp + 18432 + bd1, B1 + g1);
        CP16(sp + 27648 + bd0, B2 + g0);
        CP16(sp + 27648 + bd1, B2 + g1);
    };

    float accH[4][2][4], accG[4][2][4];
#pragma unroll
    for (int a = 0; a < 4; a++)
#pragma unroll
        for (int b = 0; b < 2; b++)
#pragma unroll
            for (int c = 0; c < 4; c++) { accH[a][b][c] = 0.f; accG[a][b][c] = 0.f; }

    const int NC = KK / 64;
    stage(0, 0); CPC();
    stage(64, 1); CPC();
#pragma unroll 1
    for (int i = 0; i < NC; i++) {
        if (i + 2 < NC) CPW1(); else CPW0();
        __syncthreads();
        if (i + 2 < NC) { stage((i + 2) * 64, (i + 2) % 3); CPC(); }
        uint32_t sb = sbase + (i % 3) * SSZ;
#pragma unroll
        for (int si = 0; si < 4; si++) {
            int s = (si + wid) & 3;               // phase rotation: break warp convoy
            uint32_t bo = (uint32_t)(s * 16 + (lane & 15)) * 144
                        + wn * 32 + (lane >> 4) * 16;
            uint32_t bf1[4], bf2[4];
            LDSM_X4T(bf1, sb + 18432 + bo);
            LDSM_X4T(bf2, sb + 27648 + bo);
#pragma unroll
            for (int mt = 0; mt < 4; mt++) {
                uint32_t ah[4];
                uint32_t ro = (uint32_t)(wm * 64 + mt * 16 + (lane & 15)) * 144
                            + (lane >> 4) * 16 + s * 32;
                LDSM_X4(ah, sb + ro);
#pragma unroll
                for (int nt = 0; nt < 2; nt++) {
                    MMA_F16(accH[mt][nt], ah, bf1[nt*2], bf1[nt*2+1]);
                    MMA_F16(accG[mt][nt], ah, bf2[nt*2], bf2[nt*2+1]);
                }
            }
        }
    }

#pragma unroll
    for (int mt = 0; mt < 4; mt++) {
        int rb = m0 + wm * 64 + mt * 16 + (lane >> 2);
#pragma unroll
        for (int h = 0; h < 2; h++) {
            int r = rb + h * 8;
            if (r >= M) continue;
            float wgt = sh ? 1.f : wv[r];
            size_t rowoff = (size_t)(rowbase + r) * NN + n0;
#pragma unroll
            for (int nt = 0; nt < 2; nt++) {
                int c = wn * 16 + nt * 8 + (lane & 3) * 2;
                float h0 = accH[mt][nt][h*2+0] + bias1[n0 + c];
                float h1 = accH[mt][nt][h*2+1] + bias1[n0 + c + 1];
                float g0 = accG[mt][nt][h*2+0] + bias2[n0 + c];
                float g1 = accG[mt][nt][h*2+1] + bias2[n0 + c + 1];
                float v0 = (h0 / (1.f + __expf(-h0))) * g0 * wgt;
                float v1 = (h1 / (1.f + __expf(-h1))) * g1 * wgt;
                *(uint32_t*)(oa + rowoff + c) = pack_h2(v0, v1);
            }
        }
    }
}

// ---------- DOWN: single-B GEMM, fp16, BK=64, BN=128, 3-stage, 2 CTAs/SM ----------
// Inner s-loop phase-rotated by warp id.
// Stage (35840 B): A 0 (128 x 144B) | B 18432 (64 x 272B)
__global__ void __launch_bounds__(256, 2)
down_gemm(const float* __restrict__ sb2, float* __restrict__ out)
{
    extern __shared__ char smem[];
    const int z = blockIdx.z;
    const bool sh = (z == NEXP);
    const int KK = sh ? SINTER : INTER;
    const int NN = DIMD;
    const int n0 = blockIdx.x * 128, m0 = blockIdx.y * 128;
    int M = T_TOKENS, rowbase = 0;
    const __half *Aa, *Bp;
    if (sh) { Aa = s_z; Bp = s_u2; }
    else {
        M = g_cnt[z];
        if (m0 >= M) return;
        rowbase = expert_off(z);
        Aa = s_a; Bp = s_w2 + (size_t)z * INTER * DIMD;
    }

    const int tid = threadIdx.x, lane = tid & 31, wid = tid >> 5;
    const int wm = wid >> 2, wn = wid & 3;
    const uint32_t sbase = smem_u32(smem);
    const int SSZ = 35840;

    const __half* ap[4];
    uint32_t adst[4];
#pragma unroll
    for (int it = 0; it < 4; it++) {
        int task = tid + it * 256, row = task >> 3, c = task & 7;
        int r = m0 + row; if (r >= M) r = M - 1;
        ap[it] = Aa + (size_t)(rowbase + r) * KK + c * 8;
        adst[it] = row * 144 + c * 16;
    }
    const int bkl = tid >> 4, bc2 = tid & 15;
    size_t bbs[4]; uint32_t bds[4];
#pragma unroll
    for (int it = 0; it < 4; it++) {
        int kl = bkl + it * 16;
        bbs[it] = (size_t)kl * NN + n0 + bc2 * 8;
        bds[it] = kl * 272 + bc2 * 16;
    }

    auto stage = [&](int k0, int st) {
        uint32_t sp = sbase + st * SSZ;
#pragma unroll
        for (int it = 0; it < 4; it++)
            CP16(sp + adst[it], ap[it] + k0);
#pragma unroll
        for (int it = 0; it < 4; it++)
            CP16(sp + 18432 + bds[it], Bp + bbs[it] + (size_t)k0 * NN);
    };

    float acc[4][4][4];
#pragma unroll
    for (int a = 0; a < 4; a++)
#pragma unroll
        for (int b = 0; b < 4; b++)
#pragma unroll
            for (int c = 0; c < 4; c++) acc[a][b][c] = 0.f;

    const int NC = KK / 64;
    stage(0, 0); CPC();
    stage(64, 1); CPC();
#pragma unroll 1
    for (int i = 0; i < NC; i++) {
        if (i + 2 < NC) CPW1(); else CPW0();
        __syncthreads();
        if (i + 2 < NC) { stage((i + 2) * 64, (i + 2) % 3); CPC(); }
        uint32_t sb = sbase + (i % 3) * SSZ;
#pragma unroll
        for (int si = 0; si < 4; si++) {
            int s = (si + wid) & 3;               // phase rotation: break warp convoy
            uint32_t bo = (uint32_t)(s * 16 + (lane & 15)) * 272
                        + wn * 64 + (lane >> 4) * 16;
            uint32_t bf0[4], bf1[4];
            LDSM_X4T(bf0, sb + 18432 + bo);
            LDSM_X4T(bf1, sb + 18432 + bo + 32);
#pragma unroll
            for (int mt = 0; mt < 4; mt++) {
                uint32_t ah[4];
                uint32_t ro = (uint32_t)(wm * 64 + mt * 16 + (lane & 15)) * 144
                            + (lane >> 4) * 16 + s * 32;
                LDSM_X4(ah, sb + ro);
                MMA_F16(acc[mt][0], ah, bf0[0], bf0[1]);
                MMA_F16(acc[mt][1], ah, bf0[2], bf0[3]);
                MMA_F16(acc[mt][2], ah, bf1[0], bf1[1]);
                MMA_F16(acc[mt][3], ah, bf1[2], bf1[3]);
            }
        }
    }

#pragma unroll
    for (int mt = 0; mt < 4; mt++) {
        int rb = m0 + wm * 64 + mt * 16 + (lane >> 2);
#pragma unroll
        for (int h = 0; h < 2; h++) {
            int r = rb + h * 8;
            if (r >= M) continue;
            size_t rowoff = (size_t)(rowbase + r) * NN + n0;
#pragma unroll
            for (int nt = 0; nt < 4; nt++) {
                int c = wn * 32 + nt * 8 + (lane & 3) * 2;
                float v0 = acc[mt][nt][h*2+0];
                float v1 = acc[mt][nt][h*2+1];
                if (sh) {
                    v0 += sb2[n0 + c]; v1 += sb2[n0 + c + 1];
                    *(float2*)(out + rowoff + c) = make_float2(v0, v1);
                } else {
                    *(float2*)(g_y + rowoff + c) = make_float2(v0, v1);
                }
            }
        }
    }
}

// ---------- combine ----------
__global__ void combine_kernel(const float* __restrict__ b2, float* __restrict__ out)
{
    __shared__ int off[NEXP];
    if (threadIdx.x < NEXP) off[threadIdx.x] = expert_off(threadIdx.x);
    __syncthreads();
    int t = blockIdx.x;
    int d = threadIdx.x * 4;
    int e0 = g_se[t*2+0], e1 = g_se[t*2+1];
    int r0 = off[e0] + g_sp[t*2+0];
    int r1 = off[e1] + g_sp[t*2+1];
    float w0 = g_sw[t*2+0], w1 = g_sw[t*2+1];
    float4 y0 = *(const float4*)&g_y[(size_t)r0 * DIMD + d];
    float4 y1 = *(const float4*)&g_y[(size_t)r1 * DIMD + d];
    float4 a0 = *(const float4*)&b2[(size_t)e0 * DIMD + d];
    float4 a1 = *(const float4*)&b2[(size_t)e1 * DIMD + d];
    float4* o = (float4*)&out[(size_t)t * DIMD + d];
    float4 c = *o;
    c.x += y0.x + y1.x + w0 * a0.x + w1 * a1.x;
    c.y += y0.y + y1.y + w0 * a0.y + w1 * a1.y;
    c.z += y0.z + y1.z + w0 * a0.z + w1 * a1.z;
    c.w += y0.w + y1.w + w0 * a0.w + w1 * a1.w;
    *o = c;
}

// ---------- launch ----------
extern "C" void kernel_launch(void* const* d_in, const int* in_sizes, int n_in,
                              void* d_out, int out_size)
{
    const float* x   = (const float*)d_in[0];
    const float* gw  = (const float*)d_in[1];
    const float* gb  = (const float*)d_in[2];
    const float* w1  = (const float*)d_in[3];
    const float* b1  = (const float*)d_in[4];
    const float* w3  = (const float*)d_in[5];
    const float* b3  = (const float*)d_in[6];
    const float* w2  = (const float*)d_in[7];
    const float* b2  = (const float*)d_in[8];
    const float* sw1 = (const float*)d_in[9];
    const float* sb1 = (const float*)d_in[10];
    const float* sw3 = (const float*)d_in[11];
    const float* sb3 = (const float*)d_in[12];
    const float* sw2 = (const float*)d_in[13];
    const float* sb2 = (const float*)d_in[14];
    float* out = (float*)d_out;

    const int SM_UP = 3 * 36864;   // 110592 (x2 = 221184 <= 228KB)
    const int SM_DN = 3 * 35840;   // 107520 (x2 = 215040 <= 228KB)
    cudaFuncSetAttribute(up_gemm,   cudaFuncAttributeMaxDynamicSharedMemorySize, SM_UP);
    cudaFuncSetAttribute(down_gemm, cudaFuncAttributeMaxDynamicSharedMemorySize, SM_DN);

    unsigned preBlocks = (unsigned)((2 * N1 + 2 * N2) / 256 + T_TOKENS * DIMD / 4 / 256);
    pre_kernel<<<preBlocks, 256>>>(w1, w3, sw1, sw3, x);                             // 0
    gate_kernel<<<T_TOKENS / 4, dim3(32, 4)>>>(x, gw, gb);                           // 1
    up_gemm<<<dim3(SINTER / 64, T_TOKENS / 128, NEXP + 2), 256, SM_UP>>>(
        b1, b3, sb1, sb3, w2, sw2);                                                  // 2 (w2/u2 split embedded)
    down_gemm<<<dim3(DIMD / 128, T_TOKENS / 128, NEXP + 1), 256, SM_DN>>>(sb2, out); // 3
    combine_kernel<<<T_TOKENS, 256>>>(b2, out);                                      // 4
}

// round 16
// speedup vs baseline: 1.0424x; 1.0424x over previous
#include <cuda_runtime.h>
#include <cuda_fp16.h>
#include <math.h>
#include <stdint.h>

#define T_TOKENS 4096
#define DIMD     1024
#define INTER    1408
#define SINTER   2816
#define NEXP     16

__device__ int   g_cnt[NEXP];
__device__ int   g_tok[NEXP * T_TOKENS];
__device__ float g_wt [NEXP * T_TOKENS];
__device__ int   g_se [T_TOKENS * 2];
__device__ int   g_sp [T_TOKENS * 2];
__device__ float g_sw [T_TOKENS * 2];
__device__ float g_y  [T_TOKENS * 2 * DIMD];

// pure fp16 storage
__device__ __half s_x [T_TOKENS * DIMD];
__device__ __half s_w1[NEXP * DIMD * INTER];
__device__ __half s_w3[NEXP * DIMD * INTER];
__device__ __half s_w2[NEXP * INTER * DIMD];
__device__ __half s_u1[DIMD * SINTER];
__device__ __half s_u3[DIMD * SINTER];
__device__ __half s_u2[SINTER * DIMD];
__device__ __half s_a [T_TOKENS * 2 * INTER];
__device__ __half s_z [T_TOKENS * SINTER];

__device__ __forceinline__ uint32_t smem_u32(const void* p) {
    uint32_t a;
    asm("{ .reg .u64 t; cvta.to.shared.u64 t, %1; cvt.u32.u64 %0, t; }" : "=r"(a) : "l"(p));
    return a;
}
#define LDSM_X4(R, a) \
    asm volatile("ldmatrix.sync.aligned.m8n8.x4.shared.b16 {%0,%1,%2,%3}, [%4];" \
        : "=r"((R)[0]), "=r"((R)[1]), "=r"((R)[2]), "=r"((R)[3]) : "r"(a))
#define LDSM_X4T(R, a) \
    asm volatile("ldmatrix.sync.aligned.m8n8.x4.trans.shared.b16 {%0,%1,%2,%3}, [%4];" \
        : "=r"((R)[0]), "=r"((R)[1]), "=r"((R)[2]), "=r"((R)[3]) : "r"(a))
#define MMA_F16(C, A, b0, b1) \
    asm volatile("mma.sync.aligned.m16n8k16.row.col.f32.f16.f16.f32 " \
        "{%0,%1,%2,%3},{%4,%5,%6,%7},{%8,%9},{%0,%1,%2,%3};" \
        : "+f"((C)[0]), "+f"((C)[1]), "+f"((C)[2]), "+f"((C)[3]) \
        : "r"((A)[0]), "r"((A)[1]), "r"((A)[2]), "r"((A)[3]), "r"(b0), "r"(b1))
#define CP16(dst, src) \
    asm volatile("cp.async.cg.shared.global [%0], [%1], 16;" :: "r"(dst), "l"(src))
#define CPC()  asm volatile("cp.async.commit_group;")
#define CPW0() asm volatile("cp.async.wait_group 0;")
#define CPW1() asm volatile("cp.async.wait_group 1;")

__device__ __forceinline__ uint32_t pack_h2(float a, float b) {
    __half2 t = __halves2half2(__float2half(a), __float2half(b));
    return *(uint32_t*)&t;
}

#define N1 ((size_t)NEXP * DIMD * INTER / 4)
#define N2 ((size_t)DIMD * SINTER / 4)

// ---------- pre: split w1,w3,u1,u3 + split x + reset g_cnt (all independent) ----------
__global__ void pre_kernel(const float* __restrict__ w1, const float* __restrict__ w3,
                           const float* __restrict__ u1, const float* __restrict__ u3,
                           const float* __restrict__ x)
{
    const size_t BS = (2 * N1 + 2 * N2) / 256;   // split blocks
    size_t b = blockIdx.x;
    if (b < BS) {
        size_t i = b * 256 + threadIdx.x;
        const float* src; __half* h; size_t o;
        if      (i < N1)          { src = w1; h = s_w1; o = i; }
        else if (i < 2*N1)        { src = w3; h = s_w3; o = i - N1; }
        else if (i < 2*N1 + N2)   { src = u1; h = s_u1; o = i - 2*N1; }
        else                      { src = u3; h = s_u3; o = i - 2*N1 - N2; }
        float4 v = *(const float4*)(src + o * 4);
        uint2 H; H.x = pack_h2(v.x, v.y); H.y = pack_h2(v.z, v.w);
        *(uint2*)(h + o * 4) = H;
    } else {
        if (b == BS && threadIdx.x < NEXP) g_cnt[threadIdx.x] = 0;
        size_t i = (b - BS) * 256 + threadIdx.x;
        float4 v = *(const float4*)(x + i * 4);
        uint2 H; H.x = pack_h2(v.x, v.y); H.y = pack_h2(v.z, v.w);
        *(uint2*)(s_x + i * 4) = H;
    }
}

// ---------- gate ----------
__global__ void gate_kernel(const float* __restrict__ x, const float* __restrict__ gw,
                            const float* __restrict__ gb)
{
    int t = blockIdx.x * blockDim.y + threadIdx.y;
    if (t >= T_TOKENS) return;
    int lane = threadIdx.x;
    float acc[NEXP];
#pragma unroll
    for (int e = 0; e < NEXP; e++) acc[e] = 0.f;
    const float* xr = x + (size_t)t * DIMD;
    for (int d = lane; d < DIMD; d += 32) {
        float xv = xr[d];
        const float* g = gw + (size_t)d * NEXP;
#pragma unroll
        for (int e = 0; e < NEXP; e++) acc[e] += xv * g[e];
    }
#pragma unroll
    for (int e = 0; e < NEXP; e++)
#pragma unroll
        for (int o = 16; o > 0; o >>= 1) acc[e] += __shfl_xor_sync(0xffffffffu, acc[e], o);
    if (lane == 0) {
        float mx = -1e30f;
#pragma unroll
        for (int e = 0; e < NEXP; e++) { acc[e] += gb[e]; mx = fmaxf(mx, acc[e]); }
        float s = 0.f;
#pragma unroll
        for (int e = 0; e < NEXP; e++) { acc[e] = expf(acc[e] - mx); s += acc[e]; }
        int b0 = 0; float v0 = -1.f;
#pragma unroll
        for (int e = 0; e < NEXP; e++) if (acc[e] > v0) { v0 = acc[e]; b0 = e; }
        int b1i = -1; float v1 = -1.f;
#pragma unroll
        for (int e = 0; e < NEXP; e++) if (e != b0 && acc[e] > v1) { v1 = acc[e]; b1i = e; }
        float w0 = v0 / s, w1 = v1 / s;
        int p0 = atomicAdd(&g_cnt[b0], 1);
        g_tok[b0 * T_TOKENS + p0] = t;  g_wt[b0 * T_TOKENS + p0] = w0;
        int p1 = atomicAdd(&g_cnt[b1i], 1);
        g_tok[b1i * T_TOKENS + p1] = t; g_wt[b1i * T_TOKENS + p1] = w1;
        g_se[t*2+0] = b0;  g_sp[t*2+0] = p0;  g_sw[t*2+0] = w0;
        g_se[t*2+1] = b1i; g_sp[t*2+1] = p1;  g_sw[t*2+1] = w1;
    }
}

// inline 16-wide prefix: offset of expert e in compact layout
__device__ __forceinline__ int expert_off(int e) {
    int s = 0;
    for (int j = 0; j < e; j++) s += g_cnt[j];
    return s;
}

// ---------- UP: dual-B SwiGLU GEMM, fp16, BK=64, 3-stage, 2 CTAs/SM ----------
// z==NEXP: shared slice. z==NEXP+1: embedded w2/u2 split.
// A-fragment double-buffered: ah[mt+1] loads before mt's MMAs (hide LDSM latency).
// Stage (36864 B): A 0 (128 x 144B, 64 k) | B1 18432 (64 x 144B) | B2 27648
__global__ void __launch_bounds__(256, 2)
up_gemm(const float* __restrict__ b1, const float* __restrict__ b3,
        const float* __restrict__ sb1, const float* __restrict__ sb3,
        const float* __restrict__ w2, const float* __restrict__ u2)
{
    extern __shared__ char smem[];
    const int z = blockIdx.z;
    const int tid = threadIdx.x;
    if (z == NEXP + 1) {                        // embedded split of w2 / u2
        const size_t total = N1 + N2;
        size_t base = ((size_t)blockIdx.y * gridDim.x + blockIdx.x) * 256 + tid;
        size_t stride = (size_t)gridDim.x * gridDim.y * 256;
        for (size_t i = base; i < total; i += stride) {
            const float* src; __half* h; size_t o;
            if (i < N1) { src = w2; h = s_w2; o = i; }
            else        { src = u2; h = s_u2; o = i - N1; }
            float4 v = *(const float4*)(src + o * 4);
            uint2 H; H.x = pack_h2(v.x, v.y); H.y = pack_h2(v.z, v.w);
            *(uint2*)(h + o * 4) = H;
        }
        return;
    }
    const bool sh = (z == NEXP);
    if (!sh && blockIdx.x >= INTER / 64) return;
    const int NN = sh ? SINTER : INTER;
    const int n0 = blockIdx.x * 64, m0 = blockIdx.y * 128;
    int M = T_TOKENS, rowbase = 0;
    const int* rowidx = nullptr; const float* wv = nullptr;
    const __half *B1, *B2;
    const float *bias1, *bias2;
    __half* oa;
    if (sh) {
        B1 = s_u1; B2 = s_u3; bias1 = sb1; bias2 = sb3; oa = s_z;
    } else {
        M = g_cnt[z];
        if (m0 >= M) return;
        rowbase = expert_off(z);
        size_t wo = (size_t)z * DIMD * INTER;
        B1 = s_w1 + wo; B2 = s_w3 + wo;
        bias1 = b1 + (size_t)z * INTER; bias2 = b3 + (size_t)z * INTER;
        rowidx = g_tok + z * T_TOKENS; wv = g_wt + z * T_TOKENS;
        oa = s_a;
    }

    const int lane = tid & 31, wid = tid >> 5;
    const int wm = wid >> 2, wn = wid & 3;
    const uint32_t sbase = smem_u32(smem);
    const int SSZ = 36864;
    const int KK = DIMD;

    const __half* ap[4];
    uint32_t adst[4];
#pragma unroll
    for (int it = 0; it < 4; it++) {
        int task = tid + it * 256, row = task >> 3, c = task & 7;
        int r = m0 + row; if (r >= M) r = M - 1;
        size_t ro = rowidx ? (size_t)rowidx[r] * KK : (size_t)r * KK;
        ap[it] = s_x + ro + c * 8;
        adst[it] = row * 144 + c * 16;
    }
    const int bkl0 = tid >> 3, bc = tid & 7;
    const size_t bb0 = (size_t)bkl0 * NN + n0 + bc * 8;
    const size_t bb1 = (size_t)(bkl0 + 32) * NN + n0 + bc * 8;
    const uint32_t bd0 = bkl0 * 144 + bc * 16;
    const uint32_t bd1 = (bkl0 + 32) * 144 + bc * 16;

    auto stage = [&](int k0, int st) {
        uint32_t sp = sbase + st * SSZ;
#pragma unroll
        for (int it = 0; it < 4; it++)
            CP16(sp + adst[it], ap[it] + k0);
        size_t g0 = bb0 + (size_t)k0 * NN, g1 = bb1 + (size_t)k0 * NN;
        CP16(sp + 18432 + bd0, B1 + g0);
        CP16(sp + 18432 + bd1, B1 + g1);
        CP16(sp + 27648 + bd0, B2 + g0);
        CP16(sp + 27648 + bd1, B2 + g1);
    };

    float accH[4][2][4], accG[4][2][4];
#pragma unroll
    for (int a = 0; a < 4; a++)
#pragma unroll
        for (int b = 0; b < 2; b++)
#pragma unroll
            for (int c = 0; c < 4; c++) { accH[a][b][c] = 0.f; accG[a][b][c] = 0.f; }

    const int NC = KK / 64;
    stage(0, 0); CPC();
    stage(64, 1); CPC();
#pragma unroll 1
    for (int i = 0; i < NC; i++) {
        if (i + 2 < NC) CPW1(); else CPW0();
        __syncthreads();
        if (i + 2 < NC) { stage((i + 2) * 64, (i + 2) % 3); CPC(); }
        uint32_t sb = sbase + (i % 3) * SSZ;
        const uint32_t arow = sb + (uint32_t)(wm * 64 + (lane & 15)) * 144
                            + (lane >> 4) * 16;
#pragma unroll
        for (int s = 0; s < 4; s++) {
            uint32_t bo = (uint32_t)(s * 16 + (lane & 15)) * 144
                        + wn * 32 + (lane >> 4) * 16;
            uint32_t bf1[4], bf2[4];
            LDSM_X4T(bf1, sb + 18432 + bo);
            LDSM_X4T(bf2, sb + 27648 + bo);
            uint32_t ah[2][4];
            LDSM_X4(ah[0], arow + s * 32);                       // mt=0 fragment
#pragma unroll
            for (int mt = 0; mt < 4; mt++) {
                int cur = mt & 1;
                if (mt < 3)                                       // prefetch next A frag
                    LDSM_X4(ah[1 - cur], arow + (mt + 1) * 16 * 144 + s * 32);
#pragma unroll
                for (int nt = 0; nt < 2; nt++) {
                    MMA_F16(accH[mt][nt], ah[cur], bf1[nt*2], bf1[nt*2+1]);
                    MMA_F16(accG[mt][nt], ah[cur], bf2[nt*2], bf2[nt*2+1]);
                }
            }
        }
    }

#pragma unroll
    for (int mt = 0; mt < 4; mt++) {
        int rb = m0 + wm * 64 + mt * 16 + (lane >> 2);
#pragma unroll
        for (int h = 0; h < 2; h++) {
            int r = rb + h * 8;
            if (r >= M) continue;
            float wgt = sh ? 1.f : wv[r];
            size_t rowoff = (size_t)(rowbase + r) * NN + n0;
#pragma unroll
            for (int nt = 0; nt < 2; nt++) {
                int c = wn * 16 + nt * 8 + (lane & 3) * 2;
                float h0 = accH[mt][nt][h*2+0] + bias1[n0 + c];
                float h1 = accH[mt][nt][h*2+1] + bias1[n0 + c + 1];
                float g0 = accG[mt][nt][h*2+0] + bias2[n0 + c];
                float g1 = accG[mt][nt][h*2+1] + bias2[n0 + c + 1];
                float v0 = (h0 / (1.f + __expf(-h0))) * g0 * wgt;
                float v1 = (h1 / (1.f + __expf(-h1))) * g1 * wgt;
                *(uint32_t*)(oa + rowoff + c) = pack_h2(v0, v1);
            }
        }
    }
}

// ---------- DOWN: single-B GEMM, fp16, BK=64, BN=128, 3-stage, 2 CTAs/SM ----------
// A-fragment double-buffered like up.
// Stage (35840 B): A 0 (128 x 144B) | B 18432 (64 x 272B)
__global__ void __launch_bounds__(256, 2)
down_gemm(const float* __restrict__ sb2, float* __restrict__ out)
{
    extern __shared__ char smem[];
    const int z = blockIdx.z;
    const bool sh = (z == NEXP);
    const int KK = sh ? SINTER : INTER;
    const int NN = DIMD;
    const int n0 = blockIdx.x * 128, m0 = blockIdx.y * 128;
    int M = T_TOKENS, rowbase = 0;
    const __half *Aa, *Bp;
    if (sh) { Aa = s_z; Bp = s_u2; }
    else {
        M = g_cnt[z];
        if (m0 >= M) return;
        rowbase = expert_off(z);
        Aa = s_a; Bp = s_w2 + (size_t)z * INTER * DIMD;
    }

    const int tid = threadIdx.x, lane = tid & 31, wid = tid >> 5;
    const int wm = wid >> 2, wn = wid & 3;
    const uint32_t sbase = smem_u32(smem);
    const int SSZ = 35840;

    const __half* ap[4];
    uint32_t adst[4];
#pragma unroll
    for (int it = 0; it < 4; it++) {
        int task = tid + it * 256, row = task >> 3, c = task & 7;
        int r = m0 + row; if (r >= M) r = M - 1;
        ap[it] = Aa + (size_t)(rowbase + r) * KK + c * 8;
        adst[it] = row * 144 + c * 16;
    }
    const int bkl = tid >> 4, bc2 = tid & 15;
    size_t bbs[4]; uint32_t bds[4];
#pragma unroll
    for (int it = 0; it < 4; it++) {
        int kl = bkl + it * 16;
        bbs[it] = (size_t)kl * NN + n0 + bc2 * 8;
        bds[it] = kl * 272 + bc2 * 16;
    }

    auto stage = [&](int k0, int st) {
        uint32_t sp = sbase + st * SSZ;
#pragma unroll
        for (int it = 0; it < 4; it++)
            CP16(sp + adst[it], ap[it] + k0);
#pragma unroll
        for (int it = 0; it < 4; it++)
            CP16(sp + 18432 + bds[it], Bp + bbs[it] + (size_t)k0 * NN);
    };

    float acc[4][4][4];
#pragma unroll
    for (int a = 0; a < 4; a++)
#pragma unroll
        for (int b = 0; b < 4; b++)
#pragma unroll
            for (int c = 0; c < 4; c++) acc[a][b][c] = 0.f;

    const int NC = KK / 64;
    stage(0, 0); CPC();
    stage(64, 1); CPC();
#pragma unroll 1
    for (int i = 0; i < NC; i++) {
        if (i + 2 < NC) CPW1(); else CPW0();
        __syncthreads();
        if (i + 2 < NC) { stage((i + 2) * 64, (i + 2) % 3); CPC(); }
        uint32_t sb = sbase + (i % 3) * SSZ;
        const uint32_t arow = sb + (uint32_t)(wm * 64 + (lane & 15)) * 144
                            + (lane >> 4) * 16;
#pragma unroll
        for (int s = 0; s < 4; s++) {
            uint32_t bo = (uint32_t)(s * 16 + (lane & 15)) * 272
                        + wn * 64 + (lane >> 4) * 16;
            uint32_t bf0[4], bf1[4];
            LDSM_X4T(bf0, sb + 18432 + bo);
            LDSM_X4T(bf1, sb + 18432 + bo + 32);
            uint32_t ah[2][4];
            LDSM_X4(ah[0], arow + s * 32);
#pragma unroll
            for (int mt = 0; mt < 4; mt++) {
                int cur = mt & 1;
                if (mt < 3)
                    LDSM_X4(ah[1 - cur], arow + (mt + 1) * 16 * 144 + s * 32);
                MMA_F16(acc[mt][0], ah[cur], bf0[0], bf0[1]);
                MMA_F16(acc[mt][1], ah[cur], bf0[2], bf0[3]);
                MMA_F16(acc[mt][2], ah[cur], bf1[0], bf1[1]);
                MMA_F16(acc[mt][3], ah[cur], bf1[2], bf1[3]);
            }
        }
    }

#pragma unroll
    for (int mt = 0; mt < 4; mt++) {
        int rb = m0 + wm * 64 + mt * 16 + (lane >> 2);
#pragma unroll
        for (int h = 0; h < 2; h++) {
            int r = rb + h * 8;
            if (r >= M) continue;
            size_t rowoff = (size_t)(rowbase + r) * NN + n0;
#pragma unroll
            for (int nt = 0; nt < 4; nt++) {
                int c = wn * 32 + nt * 8 + (lane & 3) * 2;
                float v0 = acc[mt][nt][h*2+0];
                float v1 = acc[mt][nt][h*2+1];
                if (sh) {
                    v0 += sb2[n0 + c]; v1 += sb2[n0 + c + 1];
                    *(float2*)(out + rowoff + c) = make_float2(v0, v1);
                } else {
                    *(float2*)(g_y + rowoff + c) = make_float2(v0, v1);
                }
            }
        }
    }
}

// ---------- combine ----------
__global__ void combine_kernel(const float* __restrict__ b2, float* __restrict__ out)
{
    __shared__ int off[NEXP];
    if (threadIdx.x < NEXP) off[threadIdx.x] = expert_off(threadIdx.x);
    __syncthreads();
    int t = blockIdx.x;
    int d = threadIdx.x * 4;
    int e0 = g_se[t*2+0], e1 = g_se[t*2+1];
    int r0 = off[e0] + g_sp[t*2+0];
    int r1 = off[e1] + g_sp[t*2+1];
    float w0 = g_sw[t*2+0], w1 = g_sw[t*2+1];
    float4 y0 = *(const float4*)&g_y[(size_t)r0 * DIMD + d];
    float4 y1 = *(const float4*)&g_y[(size_t)r1 * DIMD + d];
    float4 a0 = *(const float4*)&b2[(size_t)e0 * DIMD + d];
    float4 a1 = *(const float4*)&b2[(size_t)e1 * DIMD + d];
    float4* o = (float4*)&out[(size_t)t * DIMD + d];
    float4 c = *o;
    c.x += y0.x + y1.x + w0 * a0.x + w1 * a1.x;
    c.y += y0.y + y1.y + w0 * a0.y + w1 * a1.y;
    c.z += y0.z + y1.z + w0 * a0.z + w1 * a1.z;
    c.w += y0.w + y1.w + w0 * a0.w + w1 * a1.w;
    *o = c;
}

// ---------- launch ----------
extern "C" void kernel_launch(void* const* d_in, const int* in_sizes, int n_in,
                              void* d_out, int out_size)
{
    const float* x   = (const float*)d_in[0];
    const float* gw  = (const float*)d_in[1];
    const float* gb  = (const float*)d_in[2];
    const float* w1  = (const float*)d_in[3];
    const float* b1  = (const float*)d_in[4];
    const float* w3  = (const float*)d_in[5];
    const float* b3  = (const float*)d_in[6];
    const float* w2  = (const float*)d_in[7];
    const float* b2  = (const float*)d_in[8];
    const float* sw1 = (const float*)d_in[9];
    const float* sb1 = (const float*)d_in[10];
    const float* sw3 = (const float*)d_in[11];
    const float* sb3 = (const float*)d_in[12];
    const float* sw2 = (const float*)d_in[13];
    const float* sb2 = (const float*)d_in[14];
    float* out = (float*)d_out;

    const int SM_UP = 3 * 36864;   // 110592 (x2 = 221184 <= 228KB)
    const int SM_DN = 3 * 35840;   // 107520 (x2 = 215040 <= 228KB)
    cudaFuncSetAttribute(up_gemm,   cudaFuncAttributeMaxDynamicSharedMemorySize, SM_UP);
    cudaFuncSetAttribute(down_gemm, cudaFuncAttributeMaxDynamicSharedMemorySize, SM_DN);

    unsigned preBlocks = (unsigned)((2 * N1 + 2 * N2) / 256 + T_TOKENS * DIMD / 4 / 256);
    pre_kernel<<<preBlocks, 256>>>(w1, w3, sw1, sw3, x);                             // 0
    gate_kernel<<<T_TOKENS / 4, dim3(32, 4)>>>(x, gw, gb);                           // 1
    up_gemm<<<dim3(SINTER / 64, T_TOKENS / 128, NEXP + 2), 256, SM_UP>>>(
        b1, b3, sb1, sb3, w2, sw2);                                                  // 2 (w2/u2 split embedded)
    down_gemm<<<dim3(DIMD / 128, T_TOKENS / 128, NEXP + 1), 256, SM_DN>>>(sb2, out); // 3
    combine_kernel<<<T_TOKENS, 256>>>(b2, out);                                      // 4
}

// round 17
// speedup vs baseline: 1.0623x; 1.0191x over previous
#include <cuda_runtime.h>
#include <cuda_fp16.h>
#include <math.h>
#include <stdint.h>

#define T_TOKENS 4096
#define DIMD     1024
#define INTER    1408
#define SINTER   2816
#define NEXP     16

__device__ int   g_cnt[NEXP];
__device__ int   g_cnt2[NEXP];
__device__ int   g_off2[NEXP];
__device__ int4  g_mi[96];         // routed m-tile items: {expert, m0, rowbase, -}
__device__ int   g_nworkUP, g_nworkDN;
__device__ int   g_tok[NEXP * T_TOKENS];
__device__ float g_wt [NEXP * T_TOKENS];
__device__ int   g_se [T_TOKENS * 2];
__device__ int   g_sp [T_TOKENS * 2];
__device__ float g_sw [T_TOKENS * 2];
__device__ float g_y  [T_TOKENS * 2 * DIMD];

// pure fp16 storage
__device__ __half s_x [T_TOKENS * DIMD];
__device__ __half s_w1[NEXP * DIMD * INTER];
__device__ __half s_w3[NEXP * DIMD * INTER];
__device__ __half s_w2[NEXP * INTER * DIMD];
__device__ __half s_u1[DIMD * SINTER];
__device__ __half s_u3[DIMD * SINTER];
__device__ __half s_u2[SINTER * DIMD];
__device__ __half s_a [T_TOKENS * 2 * INTER];
__device__ __half s_z [T_TOKENS * SINTER];

__device__ __forceinline__ uint32_t smem_u32(const void* p) {
    uint32_t a;
    asm("{ .reg .u64 t; cvta.to.shared.u64 t, %1; cvt.u32.u64 %0, t; }" : "=r"(a) : "l"(p));
    return a;
}
#define LDSM_X4(R, a) \
    asm volatile("ldmatrix.sync.aligned.m8n8.x4.shared.b16 {%0,%1,%2,%3}, [%4];" \
        : "=r"((R)[0]), "=r"((R)[1]), "=r"((R)[2]), "=r"((R)[3]) : "r"(a))
#define LDSM_X4T(R, a) \
    asm volatile("ldmatrix.sync.aligned.m8n8.x4.trans.shared.b16 {%0,%1,%2,%3}, [%4];" \
        : "=r"((R)[0]), "=r"((R)[1]), "=r"((R)[2]), "=r"((R)[3]) : "r"(a))
#define MMA_F16(C, A, b0, b1) \
    asm volatile("mma.sync.aligned.m16n8k16.row.col.f32.f16.f16.f32 " \
        "{%0,%1,%2,%3},{%4,%5,%6,%7},{%8,%9},{%0,%1,%2,%3};" \
        : "+f"((C)[0]), "+f"((C)[1]), "+f"((C)[2]), "+f"((C)[3]) \
        : "r"((A)[0]), "r"((A)[1]), "r"((A)[2]), "r"((A)[3]), "r"(b0), "r"(b1))
#define CP16(dst, src) \
    asm volatile("cp.async.cg.shared.global [%0], [%1], 16;" :: "r"(dst), "l"(src))
#define CPC()  asm volatile("cp.async.commit_group;")
#define CPW0() asm volatile("cp.async.wait_group 0;")
#define CPW1() asm volatile("cp.async.wait_group 1;")

__device__ __forceinline__ uint32_t pack_h2(float a, float b) {
    __half2 t = __halves2half2(__float2half(a), __float2half(b));
    return *(uint32_t*)&t;
}

#define N1 ((size_t)NEXP * DIMD * INTER / 4)
#define N2 ((size_t)DIMD * SINTER / 4)
#define GATE_BLK 512
#define SPLIT_CTAS 256

// ---------- pre: gate (first blocks) + split w1,w3,u1,u3 + split x ----------
// g_cnt is zeroed by the previous replay's scan_map (statics start zeroed).
__global__ void pre_kernel(const float* __restrict__ w1, const float* __restrict__ w3,
                           const float* __restrict__ u1, const float* __restrict__ u3,
                           const float* __restrict__ x,
                           const float* __restrict__ gw, const float* __restrict__ gb)
{
    size_t b = blockIdx.x;
    int tid = threadIdx.x;
    if (b < GATE_BLK) {                                 // gate: 8 tokens per block
        int lane = tid & 31, sub = tid >> 5;
        int t = (int)b * 8 + sub;
        float acc[NEXP];
#pragma unroll
        for (int e = 0; e < NEXP; e++) acc[e] = 0.f;
        const float* xr = x + (size_t)t * DIMD;
        for (int d = lane; d < DIMD; d += 32) {
            float xv = xr[d];
            const float* g = gw + (size_t)d * NEXP;
#pragma unroll
            for (int e = 0; e < NEXP; e++) acc[e] += xv * g[e];
        }
#pragma unroll
        for (int e = 0; e < NEXP; e++)
#pragma unroll
            for (int o = 16; o > 0; o >>= 1) acc[e] += __shfl_xor_sync(0xffffffffu, acc[e], o);
        if (lane == 0) {
            float mx = -1e30f;
#pragma unroll
            for (int e = 0; e < NEXP; e++) { acc[e] += gb[e]; mx = fmaxf(mx, acc[e]); }
            float s = 0.f;
#pragma unroll
            for (int e = 0; e < NEXP; e++) { acc[e] = expf(acc[e] - mx); s += acc[e]; }
            int b0 = 0; float v0 = -1.f;
#pragma unroll
            for (int e = 0; e < NEXP; e++) if (acc[e] > v0) { v0 = acc[e]; b0 = e; }
            int b1i = -1; float v1 = -1.f;
#pragma unroll
            for (int e = 0; e < NEXP; e++) if (e != b0 && acc[e] > v1) { v1 = acc[e]; b1i = e; }
            float w0 = v0 / s, w1v = v1 / s;
            int p0 = atomicAdd(&g_cnt[b0], 1);
            g_tok[b0 * T_TOKENS + p0] = t;  g_wt[b0 * T_TOKENS + p0] = w0;
            int p1 = atomicAdd(&g_cnt[b1i], 1);
            g_tok[b1i * T_TOKENS + p1] = t; g_wt[b1i * T_TOKENS + p1] = w1v;
            g_se[t*2+0] = b0;  g_sp[t*2+0] = p0;  g_sw[t*2+0] = w0;
            g_se[t*2+1] = b1i; g_sp[t*2+1] = p1;  g_sw[t*2+1] = w1v;
        }
        return;
    }
    b -= GATE_BLK;
    const size_t BS = (2 * N1 + 2 * N2) / 256;
    if (b < BS) {
        size_t i = b * 256 + tid;
        const float* src; __half* h; size_t o;
        if      (i < N1)          { src = w1; h = s_w1; o = i; }
        else if (i < 2*N1)        { src = w3; h = s_w3; o = i - N1; }
        else if (i < 2*N1 + N2)   { src = u1; h = s_u1; o = i - 2*N1; }
        else                      { src = u3; h = s_u3; o = i - 2*N1 - N2; }
        float4 v = *(const float4*)(src + o * 4);
        uint2 H; H.x = pack_h2(v.x, v.y); H.y = pack_h2(v.z, v.w);
        *(uint2*)(h + o * 4) = H;
    } else {
        size_t i = (b - BS) * 256 + tid;
        float4 v = *(const float4*)(x + i * 4);
        uint2 H; H.x = pack_h2(v.x, v.y); H.y = pack_h2(v.z, v.w);
        *(uint2*)(s_x + i * 4) = H;
    }
}

// ---------- scan_map: build work lists, snapshot counts, reset g_cnt ----------
__global__ void scan_map()
{
    if (threadIdx.x == 0) {
        int ro = 0, mo = 0;
        for (int e = 0; e < NEXP; e++) {
            int c = g_cnt[e];
            g_cnt2[e] = c;
            g_off2[e] = ro;
            int mt = (c + 127) >> 7;
            for (int j = 0; j < mt; j++)
                g_mi[mo + j] = make_int4(e, j * 128, ro, 0);
            mo += mt;
            ro += c;
            g_cnt[e] = 0;                 // reset for next replay
        }
        g_nworkUP = 1408 + mo * 22;       // shared 32x44 tiles + routed items x 22
        g_nworkDN = 256 + mo * 8;         // shared 32x8 + routed items x 8
    }
}

// ---------- UP: dual-B SwiGLU GEMM, fp16, BK=64, 3-stage, 2 CTAs/SM ----------
// Flat work list: [0,SPLIT_CTAS) = w2/u2 split, then shared tiles, then routed tiles.
// Stage (36864 B): A 0 (128 x 144B) | B1 18432 (64 x 144B) | B2 27648
__global__ void __launch_bounds__(256, 2)
up_gemm(const float* __restrict__ b1, const float* __restrict__ b3,
        const float* __restrict__ sb1, const float* __restrict__ sb3,
        const float* __restrict__ w2, const float* __restrict__ u2)
{
    extern __shared__ char smem[];
    const int tid = threadIdx.x;
    int w = blockIdx.x;
    if (w < SPLIT_CTAS) {                        // embedded split of w2 / u2
        const size_t total = N1 + N2;
        size_t base = (size_t)w * 256 + tid;
        size_t stride = (size_t)SPLIT_CTAS * 256;
        for (size_t i = base; i < total; i += stride) {
            const float* src; __half* h; size_t o;
            if (i < N1) { src = w2; h = s_w2; o = i; }
            else        { src = u2; h = s_u2; o = i - N1; }
            float4 v = *(const float4*)(src + o * 4);
            uint2 H; H.x = pack_h2(v.x, v.y); H.y = pack_h2(v.z, v.w);
            *(uint2*)(h + o * 4) = H;
        }
        return;
    }
    w -= SPLIT_CTAS;
    if (w >= g_nworkUP) return;

    bool sh; int n0, m0, M, rowbase = 0, e = 0;
    if (w < 1408) {                              // shared expert tiles
        sh = true;
        m0 = (w / 44) * 128; n0 = (w % 44) * 64; M = T_TOKENS;
    } else {
        sh = false;
        int r = w - 1408;
        int4 mi = g_mi[r / 22];
        e = mi.x; m0 = mi.y; rowbase = mi.z;
        n0 = (r % 22) * 64;
        M = g_cnt2[e];
    }
    const int NN = sh ? SINTER : INTER;
    const int* rowidx = nullptr; const float* wv = nullptr;
    const __half *B1, *B2;
    const float *bias1, *bias2;
    __half* oa;
    if (sh) {
        B1 = s_u1; B2 = s_u3; bias1 = sb1; bias2 = sb3; oa = s_z;
    } else {
        size_t wo = (size_t)e * DIMD * INTER;
        B1 = s_w1 + wo; B2 = s_w3 + wo;
        bias1 = b1 + (size_t)e * INTER; bias2 = b3 + (size_t)e * INTER;
        rowidx = g_tok + e * T_TOKENS; wv = g_wt + e * T_TOKENS;
        oa = s_a;
    }

    const int lane = tid & 31, wid = tid >> 5;
    const int wm = wid >> 2, wn = wid & 3;
    const uint32_t sbase = smem_u32(smem);
    const int SSZ = 36864;
    const int KK = DIMD;

    const __half* ap[4];
    uint32_t adst[4];
#pragma unroll
    for (int it = 0; it < 4; it++) {
        int task = tid + it * 256, row = task >> 3, c = task & 7;
        int r = m0 + row; if (r >= M) r = M - 1;
        size_t ro = rowidx ? (size_t)rowidx[r] * KK : (size_t)r * KK;
        ap[it] = s_x + ro + c * 8;
        adst[it] = row * 144 + c * 16;
    }
    const int bkl0 = tid >> 3, bc = tid & 7;
    const size_t bb0 = (size_t)bkl0 * NN + n0 + bc * 8;
    const size_t bb1 = (size_t)(bkl0 + 32) * NN + n0 + bc * 8;
    const uint32_t bd0 = bkl0 * 144 + bc * 16;
    const uint32_t bd1 = (bkl0 + 32) * 144 + bc * 16;

    auto stage = [&](int k0, int st) {
        uint32_t sp = sbase + st * SSZ;
#pragma unroll
        for (int it = 0; it < 4; it++)
            CP16(sp + adst[it], ap[it] + k0);
        size_t g0 = bb0 + (size_t)k0 * NN, g1 = bb1 + (size_t)k0 * NN;
        CP16(sp + 18432 + bd0, B1 + g0);
        CP16(sp + 18432 + bd1, B1 + g1);
        CP16(sp + 27648 + bd0, B2 + g0);
        CP16(sp + 27648 + bd1, B2 + g1);
    };

    float accH[4][2][4], accG[4][2][4];
#pragma unroll
    for (int a = 0; a < 4; a++)
#pragma unroll
        for (int b = 0; b < 2; b++)
#pragma unroll
            for (int c = 0; c < 4; c++) { accH[a][b][c] = 0.f; accG[a][b][c] = 0.f; }

    const int NC = KK / 64;
    stage(0, 0); CPC();
    stage(64, 1); CPC();
#pragma unroll 1
    for (int i = 0; i < NC; i++) {
        if (i + 2 < NC) CPW1(); else CPW0();
        __syncthreads();
        if (i + 2 < NC) { stage((i + 2) * 64, (i + 2) % 3); CPC(); }
        uint32_t sb = sbase + (i % 3) * SSZ;
        const uint32_t arow = sb + (uint32_t)(wm * 64 + (lane & 15)) * 144
                            + (lane >> 4) * 16;
#pragma unroll
        for (int s = 0; s < 4; s++) {
            uint32_t bo = (uint32_t)(s * 16 + (lane & 15)) * 144
                        + wn * 32 + (lane >> 4) * 16;
            uint32_t bf1[4], bf2[4];
            LDSM_X4T(bf1, sb + 18432 + bo);
            LDSM_X4T(bf2, sb + 27648 + bo);
            uint32_t ah[2][4];
            LDSM_X4(ah[0], arow + s * 32);
#pragma unroll
            for (int mt = 0; mt < 4; mt++) {
                int cur = mt & 1;
                if (mt < 3)
                    LDSM_X4(ah[1 - cur], arow + (mt + 1) * 16 * 144 + s * 32);
#pragma unroll
                for (int nt = 0; nt < 2; nt++) {
                    MMA_F16(accH[mt][nt], ah[cur], bf1[nt*2], bf1[nt*2+1]);
                    MMA_F16(accG[mt][nt], ah[cur], bf2[nt*2], bf2[nt*2+1]);
                }
            }
        }
    }

#pragma unroll
    for (int mt = 0; mt < 4; mt++) {
        int rb = m0 + wm * 64 + mt * 16 + (lane >> 2);
#pragma unroll
        for (int h = 0; h < 2; h++) {
            int r = rb + h * 8;
            if (r >= M) continue;
            float wgt = sh ? 1.f : wv[r];
            size_t rowoff = (size_t)(rowbase + r) * NN + n0;
#pragma unroll
            for (int nt = 0; nt < 2; nt++) {
                int c = wn * 16 + nt * 8 + (lane & 3) * 2;
                float h0 = accH[mt][nt][h*2+0] + bias1[n0 + c];
                float h1 = accH[mt][nt][h*2+1] + bias1[n0 + c + 1];
                float g0 = accG[mt][nt][h*2+0] + bias2[n0 + c];
                float g1 = accG[mt][nt][h*2+1] + bias2[n0 + c + 1];
                float v0 = (h0 / (1.f + __expf(-h0))) * g0 * wgt;
                float v1 = (h1 / (1.f + __expf(-h1))) * g1 * wgt;
                *(uint32_t*)(oa + rowoff + c) = pack_h2(v0, v1);
            }
        }
    }
}

// ---------- DOWN: single-B GEMM, fp16, BK=64, BN=128, 3-stage, 2 CTAs/SM ----------
// Flat work list: shared 32x8 tiles first, then routed items x 8 n-tiles.
// Stage (35840 B): A 0 (128 x 144B) | B 18432 (64 x 272B)
__global__ void __launch_bounds__(256, 2)
down_gemm(const float* __restrict__ sb2, float* __restrict__ out)
{
    extern __shared__ char smem[];
    int w = blockIdx.x;
    if (w >= g_nworkDN) return;
    bool sh; int n0, m0, M, rowbase = 0, e = 0;
    if (w < 256) {
        sh = true;
        m0 = (w / 8) * 128; n0 = (w % 8) * 128; M = T_TOKENS;
    } else {
        sh = false;
        int r = w - 256;
        int4 mi = g_mi[r / 8];
        e = mi.x; m0 = mi.y; rowbase = mi.z;
        n0 = (r % 8) * 128;
        M = g_cnt2[e];
    }
    const int KK = sh ? SINTER : INTER;
    const int NN = DIMD;
    const __half *Aa, *Bp;
    if (sh) { Aa = s_z; Bp = s_u2; }
    else    { Aa = s_a; Bp = s_w2 + (size_t)e * INTER * DIMD; }

    const int tid = threadIdx.x, lane = tid & 31, wid = tid >> 5;
    const int wm = wid >> 2, wn = wid & 3;
    const uint32_t sbase = smem_u32(smem);
    const int SSZ = 35840;

    const __half* ap[4];
    uint32_t adst[4];
#pragma unroll
    for (int it = 0; it < 4; it++) {
        int task = tid + it * 256, row = task >> 3, c = task & 7;
        int r = m0 + row; if (r >= M) r = M - 1;
        ap[it] = Aa + (size_t)(rowbase + r) * KK + c * 8;
        adst[it] = row * 144 + c * 16;
    }
    const int bkl = tid >> 4, bc2 = tid & 15;
    size_t bbs[4]; uint32_t bds[4];
#pragma unroll
    for (int it = 0; it < 4; it++) {
        int kl = bkl + it * 16;
        bbs[it] = (size_t)kl * NN + n0 + bc2 * 8;
        bds[it] = kl * 272 + bc2 * 16;
    }

    auto stage = [&](int k0, int st) {
        uint32_t sp = sbase + st * SSZ;
#pragma unroll
        for (int it = 0; it < 4; it++)
            CP16(sp + adst[it], ap[it] + k0);
#pragma unroll
        for (int it = 0; it < 4; it++)
            CP16(sp + 18432 + bds[it], Bp + bbs[it] + (size_t)k0 * NN);
    };

    float acc[4][4][4];
#pragma unroll
    for (int a = 0; a < 4; a++)
#pragma unroll
        for (int b = 0; b < 4; b++)
#pragma unroll
            for (int c = 0; c < 4; c++) acc[a][b][c] = 0.f;

    const int NC = KK / 64;
    stage(0, 0); CPC();
    stage(64, 1); CPC();
#pragma unroll 1
    for (int i = 0; i < NC; i++) {
        if (i + 2 < NC) CPW1(); else CPW0();
        __syncthreads();
        if (i + 2 < NC) { stage((i + 2) * 64, (i + 2) % 3); CPC(); }
        uint32_t sb = sbase + (i % 3) * SSZ;
        const uint32_t arow = sb + (uint32_t)(wm * 64 + (lane & 15)) * 144
                            + (lane >> 4) * 16;
#pragma unroll
        for (int s = 0; s < 4; s++) {
            uint32_t bo = (uint32_t)(s * 16 + (lane & 15)) * 272
                        + wn * 64 + (lane >> 4) * 16;
            uint32_t bf0[4], bf1[4];
            LDSM_X4T(bf0, sb + 18432 + bo);
            LDSM_X4T(bf1, sb + 18432 + bo + 32);
            uint32_t ah[2][4];
            LDSM_X4(ah[0], arow + s * 32);
#pragma unroll
            for (int mt = 0; mt < 4; mt++) {
                int cur = mt & 1;
                if (mt < 3)
                    LDSM_X4(ah[1 - cur], arow + (mt + 1) * 16 * 144 + s * 32);
                MMA_F16(acc[mt][0], ah[cur], bf0[0], bf0[1]);
                MMA_F16(acc[mt][1], ah[cur], bf0[2], bf0[3]);
                MMA_F16(acc[mt][2], ah[cur], bf1[0], bf1[1]);
                MMA_F16(acc[mt][3], ah[cur], bf1[2], bf1[3]);
            }
        }
    }

#pragma unroll
    for (int mt = 0; mt < 4; mt++) {
        int rb = m0 + wm * 64 + mt * 16 + (lane >> 2);
#pragma unroll
        for (int h = 0; h < 2; h++) {
            int r = rb + h * 8;
            if (r >= M) continue;
            size_t rowoff = (size_t)(rowbase + r) * NN + n0;
#pragma unroll
            for (int nt = 0; nt < 4; nt++) {
                int c = wn * 32 + nt * 8 + (lane & 3) * 2;
                float v0 = acc[mt][nt][h*2+0];
                float v1 = acc[mt][nt][h*2+1];
                if (sh) {
                    v0 += sb2[n0 + c]; v1 += sb2[n0 + c + 1];
                    *(float2*)(out + rowoff + c) = make_float2(v0, v1);
                } else {
                    *(float2*)(g_y + rowoff + c) = make_float2(v0, v1);
                }
            }
        }
    }
}

// ---------- combine ----------
__global__ void combine_kernel(const float* __restrict__ b2, float* __restrict__ out)
{
    int t = blockIdx.x;
    int d = threadIdx.x * 4;
    int e0 = g_se[t*2+0], e1 = g_se[t*2+1];
    int r0 = g_off2[e0] + g_sp[t*2+0];
    int r1 = g_off2[e1] + g_sp[t*2+1];
    float w0 = g_sw[t*2+0], w1 = g_sw[t*2+1];
    float4 y0 = *(const float4*)&g_y[(size_t)r0 * DIMD + d];
    float4 y1 = *(const float4*)&g_y[(size_t)r1 * DIMD + d];
    float4 a0 = *(const float4*)&b2[(size_t)e0 * DIMD + d];
    float4 a1 = *(const float4*)&b2[(size_t)e1 * DIMD + d];
    float4* o = (float4*)&out[(size_t)t * DIMD + d];
    float4 c = *o;
    c.x += y0.x + y1.x + w0 * a0.x + w1 * a1.x;
    c.y += y0.y + y1.y + w0 * a0.y + w1 * a1.y;
    c.z += y0.z + y1.z + w0 * a0.z + w1 * a1.z;
    c.w += y0.w + y1.w + w0 * a0.w + w1 * a1.w;
    *o = c;
}

// ---------- launch ----------
extern "C" void kernel_launch(void* const* d_in, const int* in_sizes, int n_in,
                              void* d_out, int out_size)
{
    const float* x   = (const float*)d_in[0];
    const float* gw  = (const float*)d_in[1];
    const float* gb  = (const float*)d_in[2];
    const float* w1  = (const float*)d_in[3];
    const float* b1  = (const float*)d_in[4];
    const float* w3  = (const float*)d_in[5];
    const float* b3  = (const float*)d_in[6];
    const float* w2  = (const float*)d_in[7];
    const float* b2  = (const float*)d_in[8];
    const float* sw1 = (const float*)d_in[9];
    const float* sb1 = (const float*)d_in[10];
    const float* sw3 = (const float*)d_in[11];
    const float* sb3 = (const float*)d_in[12];
    const float* sw2 = (const float*)d_in[13];
    const float* sb2 = (const float*)d_in[14];
    float* out = (float*)d_out;

    const int SM_UP = 3 * 36864;   // 110592 (x2 = 221184 <= 228KB)
    const int SM_DN = 3 * 35840;   // 107520 (x2 = 215040 <= 228KB)
    cudaFuncSetAttribute(up_gemm,   cudaFuncAttributeMaxDynamicSharedMemorySize, SM_UP);
    cudaFuncSetAttribute(down_gemm, cudaFuncAttributeMaxDynamicSharedMemorySize, SM_DN);

    unsigned preBlocks = (unsigned)(GATE_BLK + (2 * N1 + 2 * N2) / 256
                                    + T_TOKENS * DIMD / 4 / 256);
    pre_kernel<<<preBlocks, 256>>>(w1, w3, sw1, sw3, x, gw, gb);        // 0
    scan_map<<<1, 32>>>();                                              // 1
    up_gemm<<<SPLIT_CTAS + 1408 + 80 * 22, 256, SM_UP>>>(
        b1, b3, sb1, sb3, w2, sw2);                                     // 2
    down_gemm<<<256 + 80 * 8, 256, SM_DN>>>(sb2, out);                  // 3
    combine_kernel<<<T_TOKENS, 256>>>(b2, out);                         // 4
}